// round 17
// baseline (speedup 1.0000x reference)
#include <cuda_runtime.h>
#include <cuda_bf16.h>
#include <cuda_fp16.h>
#include <math.h>
#include <stdint.h>

#define Bb 16
#define Hh 512
#define Ll 4096
#define NC 4096
#define LAMBDA 0.001f

// Scratch (no runtime allocation allowed)
__device__ float4   g_Tab[(size_t)Hh * 4096];               // per-POSITION pointwise table
__device__ uint32_t g_Yhi[(size_t)Bb * Hh * Ll / 2];        // fp16x2 of gelu(conv+skip)
__device__ uint32_t g_Whi[Hh * Hh / 2];                     // W fp16x2, row-major [v][k]

typedef unsigned long long ull;

__device__ __forceinline__ float2 cadd(float2 a, float2 b) { return make_float2(a.x + b.x, a.y + b.y); }
__device__ __forceinline__ float2 csub(float2 a, float2 b) { return make_float2(a.x - b.x, a.y - b.y); }
__device__ __forceinline__ float2 cmul(float2 a, float2 b) {
    return make_float2(a.x * b.x - a.y * b.y, a.x * b.y + a.y * b.x);
}
__device__ __forceinline__ float2 conjf2(float2 a) { return make_float2(a.x, -a.y); }
__device__ __forceinline__ float2 cscale(float2 a, float s) { return make_float2(a.x * s, a.y * s); }

__device__ __forceinline__ int sidx(int n) { return n + (n >> 4); }
#define SMSZ (4096 + 256)

// 4-digit octal reversal (12-bit), involutive
__device__ __forceinline__ int rev4(int k) {
    return ((k & 7) << 9) | (((k >> 3) & 7) << 6) | (((k >> 6) & 7) << 3) | ((k >> 9) & 7);
}

// ---------------------------------------------------------------------------
// packed f32x2 helpers (pattern validated on this harness in round 2)
// ---------------------------------------------------------------------------
__device__ __forceinline__ ull pk(float x, float y) {
    ull r; asm("mov.b64 %0, {%1,%2};" : "=l"(r) : "f"(x), "f"(y)); return r;
}
__device__ __forceinline__ float2 up(ull v) {
    float2 r; asm("mov.b64 {%0,%1}, %2;" : "=f"(r.x), "=f"(r.y) : "l"(v)); return r;
}
__device__ __forceinline__ ull f2(ull a, ull b, ull c) {
    ull d; asm("fma.rn.f32x2 %0, %1, %2, %3;" : "=l"(d) : "l"(a), "l"(b), "l"(c)); return d;
}
__device__ __forceinline__ ull swp(ull v) { float2 t = up(v); return pk(t.y, t.x); }

#define CQ 0.70710678118654752440f

// packed radix-8 butterfly; verified component-wise against scalar version.
// fwd rot = (1,-1) [d -> (y,-x)], inv rot = (-1,1) [d -> (-y,x)]
template <bool INV>
__device__ __forceinline__ void radix8p(ull a[8]) {
    const ull ONE  = pk(1.f, 1.f);
    const ull NEG  = pk(-1.f, -1.f);
    const ull ZERO = pk(0.f, 0.f);
    const ull ROT  = INV ? pk(-1.f, 1.f) : pk(1.f, -1.f);
    const ull A1   = pk(CQ, CQ);
    const ull B1   = INV ? pk(-CQ, CQ) : pk(CQ, -CQ);
    const ull A3   = pk(-CQ, -CQ);
    const ull B3   = INV ? pk(-CQ, CQ) : pk(CQ, -CQ);

    ull t0 = f2(a[4], ONE, a[0]);
    ull t1 = f2(a[4], NEG, a[0]);
    ull t2 = f2(a[6], ONE, a[2]);
    ull d26 = f2(a[6], NEG, a[2]);
    ull t3 = f2(swp(d26), ROT, ZERO);
    ull E0 = f2(t2, ONE, t0), E2 = f2(t2, NEG, t0);
    ull E1 = f2(t3, ONE, t1), E3 = f2(t3, NEG, t1);
    ull s0 = f2(a[5], ONE, a[1]);
    ull s1 = f2(a[5], NEG, a[1]);
    ull s2 = f2(a[7], ONE, a[3]);
    ull d37 = f2(a[7], NEG, a[3]);
    ull s3 = f2(swp(d37), ROT, ZERO);
    ull O0 = f2(s2, ONE, s0), O2 = f2(s2, NEG, s0);
    ull O1 = f2(s3, ONE, s1), O3 = f2(s3, NEG, s1);
    ull O1w = f2(O1, A1, f2(swp(O1), B1, ZERO));
    ull O2w = f2(swp(O2), ROT, ZERO);
    ull O3w = f2(O3, A3, f2(swp(O3), B3, ZERO));
    a[0] = f2(O0, ONE, E0);  a[4] = f2(O0, NEG, E0);
    a[1] = f2(O1w, ONE, E1); a[5] = f2(O1w, NEG, E1);
    a[2] = f2(O2w, ONE, E2); a[6] = f2(O2w, NEG, E2);
    a[3] = f2(O3w, ONE, E3); a[7] = f2(O3w, NEG, E3);
}

// inverse packed radix-8 computing ONLY outputs 0..3
__device__ __forceinline__ void radix8p_inv_low(ull a[8]) {
    const ull ONE  = pk(1.f, 1.f);
    const ull NEG  = pk(-1.f, -1.f);
    const ull ZERO = pk(0.f, 0.f);
    const ull ROT  = pk(-1.f, 1.f);
    const ull A1   = pk(CQ, CQ);
    const ull B1   = pk(-CQ, CQ);
    const ull A3   = pk(-CQ, -CQ);
    const ull B3   = pk(-CQ, CQ);

    ull t0 = f2(a[4], ONE, a[0]);
    ull t1 = f2(a[4], NEG, a[0]);
    ull t2 = f2(a[6], ONE, a[2]);
    ull d26 = f2(a[6], NEG, a[2]);
    ull t3 = f2(swp(d26), ROT, ZERO);
    ull E0 = f2(t2, ONE, t0), E2 = f2(t2, NEG, t0);
    ull E1 = f2(t3, ONE, t1), E3 = f2(t3, NEG, t1);
    ull s0 = f2(a[5], ONE, a[1]);
    ull s1 = f2(a[5], NEG, a[1]);
    ull s2 = f2(a[7], ONE, a[3]);
    ull d37 = f2(a[7], NEG, a[3]);
    ull s3 = f2(swp(d37), ROT, ZERO);
    ull O0 = f2(s2, ONE, s0), O2 = f2(s2, NEG, s0);
    ull O1 = f2(s3, ONE, s1), O3 = f2(s3, NEG, s1);
    ull O1w = f2(O1, A1, f2(swp(O1), B1, ZERO));
    ull O2w = f2(swp(O2), ROT, ZERO);
    ull O3w = f2(O3, A3, f2(swp(O3), B3, ZERO));
    a[0] = f2(O0, ONE, E0);
    a[1] = f2(O1w, ONE, E1);
    a[2] = f2(O2w, ONE, E2);
    a[3] = f2(O3w, ONE, E3);
}

// scalar twiddle applied at packed boundary (serial chain = low regs)
__device__ __forceinline__ void twiddle8p(ull a[8], float ang) {
    float sv, cv; __sincosf(ang, &sv, &cv);
    float2 w1 = make_float2(cv, sv), w = w1;
    { float2 v = cmul(up(a[1]), w); a[1] = pk(v.x, v.y); }
#pragma unroll
    for (int i = 2; i < 8; i++) {
        w = cmul(w, w1);
        float2 v = cmul(up(a[i]), w);
        a[i] = pk(v.x, v.y);
    }
}

template <bool INV, int LOGS, bool POST>
__device__ __forceinline__ void stage_gp(float2* z, int t) {
    constexpr int S = 1 << LOGS;
    int j = t & (S - 1);
    int base = ((t >> LOGS) << (LOGS + 3)) + j;
    ull a[8];
#pragma unroll
    for (int i = 0; i < 8; i++) a[i] = *(const ull*)(z + sidx(base + i * S));
    bool tw = (S > 1) && (j != 0);
    float ang = (INV ? 6.283185307179586f : -6.283185307179586f) * (float)j / (float)(8 * S);
    if (!POST && tw) twiddle8p(a, ang);
    radix8p<INV>(a);
    if (POST && tw) twiddle8p(a, ang);
#pragma unroll
    for (int i = 0; i < 8; i++) *(ull*)(z + sidx(base + i * S)) = a[i];
}

// forward DIF first stage: inputs in[0..3], upper half zero
__device__ __forceinline__ void fwd_first_stage_p(float2* z, int t, const float2 in[4]) {
    ull a[8];
#pragma unroll
    for (int i = 0; i < 4; i++) a[i] = pk(in[i].x, in[i].y);
#pragma unroll
    for (int i = 4; i < 8; i++) a[i] = pk(0.f, 0.f);
    radix8p<false>(a);
    if (t) twiddle8p(a, -6.283185307179586f * (float)t / 4096.0f);
#pragma unroll
    for (int i = 0; i < 8; i++) *(ull*)(z + sidx(t + i * 512)) = a[i];
}

// ---------------------------------------------------------------------------
// Kernel A: squash + DIF rfft(8192 packed) -> per-position table g_Tab
// ---------------------------------------------------------------------------
__global__ __launch_bounds__(512, 2) void build_kf_kernel(const float* __restrict__ kparam) {
    __shared__ float2 z[SMSZ];
    int t = threadIdx.x, h = blockIdx.x;
    const float2* kp2 = (const float2*)(kparam + (size_t)h * Ll);

    {
        float2 in[4];
#pragma unroll
        for (int i = 0; i < 4; i++) {
            float2 v = kp2[t + 512 * i];
            float s0 = fabsf(v.x) - LAMBDA; float aa = (s0 > 0.f) ? copysignf(s0, v.x) : 0.f;
            float s1 = fabsf(v.y) - LAMBDA; float bb = (s1 > 0.f) ? copysignf(s1, v.y) : 0.f;
            in[i] = make_float2(aa, bb);
        }
        fwd_first_stage_p(z, t, in);
    }
    __syncthreads();
    stage_gp<false, 6, true>(z, t); __syncthreads();
    stage_gp<false, 3, true>(z, t); __syncwarp();   // S=8 -> S=1: octet-local
    stage_gp<false, 0, true>(z, t); __syncthreads();

    float4* tab = g_Tab + (size_t)h * 4096;
    const float scale = 1.0f / (float)NC;
    for (int p = t; p < 4096; p += 512) {
        int k = rev4(p);
        float4 e;
        if (k == 0) {
            float2 Z0 = z[sidx(0)];
            float K0 = (Z0.x + Z0.y) * scale;
            float KN = (Z0.x - Z0.y) * scale;
            e = make_float4(0.5f * (K0 + KN), 0.f, 0.f, 0.5f * (K0 - KN));
        } else {
            int kk = (k <= 2048) ? k : 4096 - k;
            float2 Zk = z[sidx(rev4(kk))];
            float2 Zj = z[sidx(rev4(4096 - kk))];
            float2 E = make_float2(0.5f * (Zk.x + Zj.x),  0.5f * (Zk.y - Zj.y));
            float2 O = make_float2(0.5f * (Zk.y + Zj.y), -0.5f * (Zk.x - Zj.x));
            float sv, cv; __sincosf(-3.14159265358979f * (float)kk / (float)NC, &sv, &cv);
            float2 W  = make_float2(cv, sv);
            float2 Wj = make_float2(-cv, sv);
            float2 Kk = cscale(cadd(E, cmul(W, O)), scale);
            float2 Kj = cscale(cadd(conjf2(E), cmul(Wj, conjf2(O))), scale);
            float s = sv, c = cv;
            if (k <= 2048) {
                e.x = 0.5f * ((1.f + s) * Kk.x + (1.f - s) * Kj.x);
                e.y = 0.5f * ((1.f + s) * Kk.y - (1.f - s) * Kj.y);
                e.z = -0.5f * c * (Kk.y + Kj.y);
                e.w =  0.5f * c * (Kk.x - Kj.x);
            } else {
                e.x = 0.5f * ((1.f + s) * Kj.x + (1.f - s) * Kk.x);
                e.y = 0.5f * ((1.f + s) * Kj.y - (1.f - s) * Kk.y);
                e.z =  0.5f * c * (Kj.y + Kk.y);
                e.w = -0.5f * c * (Kj.x - Kk.x);
            }
        }
        tab[p] = e;
    }
}

// ---------------------------------------------------------------------------
// Kernel A2: W fp32 -> fp16 (once)
// ---------------------------------------------------------------------------
__global__ void split_w_kernel(const float* __restrict__ W) {
    int i = blockIdx.x * 256 + threadIdx.x;
    float4 w4 = *(const float4*)(W + 4 * (size_t)i);
    __half h0 = __float2half(w4.x);
    __half h1 = __float2half(w4.y);
    __half h2 = __float2half(w4.z);
    __half h3 = __float2half(w4.w);
    uint2 hp;
    hp.x = (uint32_t)__half_as_ushort(h0) | ((uint32_t)__half_as_ushort(h1) << 16);
    hp.y = (uint32_t)__half_as_ushort(h2) | ((uint32_t)__half_as_ushort(h3) << 16);
    *(uint2*)(g_Whi + 2 * (size_t)i) = hp;
}

// ---------------------------------------------------------------------------
// Kernel B: DIF fwd -> per-position pointwise (z->z2) -> DIT inv (pruned last
// stage in regs) -> +D*u -> GELU -> fp16.  Packed-f32x2 butterflies.
// ---------------------------------------------------------------------------
#define CONV_SMEM (2 * SMSZ * (int)sizeof(float2))   // 69632

__global__ __launch_bounds__(512, 3) void conv_kernel(const float* __restrict__ u,
                                                      const float* __restrict__ D) {
    extern __shared__ float2 zz[];
    float2* z  = zz;
    float2* z2 = zz + SMSZ;
    int t = threadIdx.x, h = blockIdx.x, b = blockIdx.y;
    const float2* u2 = (const float2*)(u + ((size_t)(b * Hh + h)) * Ll);

    {
        float2 in[4];
#pragma unroll
        for (int i = 0; i < 4; i++) in[i] = u2[t + 512 * i];
        fwd_first_stage_p(z, t, in);
    }
    __syncthreads();
    stage_gp<false, 6, true>(z, t); __syncthreads();
    stage_gp<false, 3, true>(z, t); __syncwarp();   // S=8 -> S=1: octet-local
    stage_gp<false, 0, true>(z, t); __syncthreads();

    const float4* tab = g_Tab + (size_t)h * 4096;
    for (int p = t; p < 4096; p += 512) {
        int q = rev4((4096 - rev4(p)) & 4095);
        float2 Zp = z[sidx(p)];
        float2 Zq = z[sidx(q)];
        float4 tA = tab[p];
        float nx = tA.x * Zp.x - tA.y * Zp.y + tA.z * Zq.x + tA.w * Zq.y;
        float ny = tA.x * Zp.y + tA.y * Zp.x + tA.w * Zq.x - tA.z * Zq.y;
        z2[sidx(p)] = make_float2(nx, ny);
    }
    __syncthreads();

    stage_gp<true, 0, false>(z2, t); __syncwarp();  // S=1 -> S=8: octet-local
    stage_gp<true, 3, false>(z2, t); __syncthreads();
    stage_gp<true, 6, false>(z2, t); __syncthreads();

    ull a[8];
#pragma unroll
    for (int i = 0; i < 8; i++) a[i] = *(const ull*)(z2 + sidx(t + i * 512));
    if (t) twiddle8p(a, 6.283185307179586f * (float)t / 4096.0f);
    radix8p_inv_low(a);     // only outputs 0..3 needed (n < 2048)

    float dcoef = D[h];
    uint32_t* yh = g_Yhi + ((size_t)(b * Hh + h)) * (Ll / 2);
    const float INV_SQRT2 = 0.70710678118654752f;
#pragma unroll
    for (int i = 0; i < 4; i++) {
        int n = t + 512 * i;
        float2 uv = u2[n];
        float2 av = up(a[i]);
        float y0 = av.x + dcoef * uv.x;
        float y1 = av.y + dcoef * uv.y;
        y0 = 0.5f * y0 * (1.0f + erff(y0 * INV_SQRT2));
        y1 = 0.5f * y1 * (1.0f + erff(y1 * INV_SQRT2));
        __half h0 = __float2half(y0);
        __half h1 = __float2half(y1);
        yh[n] = (uint32_t)__half_as_ushort(h0) | ((uint32_t)__half_as_ushort(h1) << 16);
    }
}

// ---------------------------------------------------------------------------
// Kernel C: HMMA fp16 GEMM, single term (Whi*Yhi), warp tile 64x32,
// CTA 128x128, 8 warps 2x4, 3-stage cp.async pipeline (round-11 validated)
// ---------------------------------------------------------------------------
#define HC 32
#define NHC 16
#define A_ST 80
#define ST_SZ 18432
#define GEMM_SMEM (3 * ST_SZ)   // 55296

__device__ __forceinline__ uint32_t smem_u32(const void* p) {
    uint32_t a;
    asm("{ .reg .u64 t; cvta.to.shared.u64 t, %1; cvt.u32.u64 %0, t; }" : "=r"(a) : "l"(p));
    return a;
}
__device__ __forceinline__ void cpa16(uint32_t dst, const void* src) {
    asm volatile("cp.async.cg.shared.global [%0], [%1], 16;" :: "r"(dst), "l"(src));
}
__device__ __forceinline__ void ldsm4(uint32_t r[4], uint32_t addr) {
    asm volatile("ldmatrix.sync.aligned.m8n8.x4.shared.b16 {%0,%1,%2,%3}, [%4];"
                 : "=r"(r[0]), "=r"(r[1]), "=r"(r[2]), "=r"(r[3]) : "r"(addr));
}
__device__ __forceinline__ void ldsm4t(uint32_t r[4], uint32_t addr) {
    asm volatile("ldmatrix.sync.aligned.m8n8.x4.trans.shared.b16 {%0,%1,%2,%3}, [%4];"
                 : "=r"(r[0]), "=r"(r[1]), "=r"(r[2]), "=r"(r[3]) : "r"(addr));
}
__device__ __forceinline__ void mma16816h(float c[4], const uint32_t a[4], const uint32_t b[2]) {
    asm volatile(
        "mma.sync.aligned.m16n8k16.row.col.f32.f16.f16.f32 "
        "{%0,%1,%2,%3}, {%4,%5,%6,%7}, {%8,%9}, {%0,%1,%2,%3};"
        : "+f"(c[0]), "+f"(c[1]), "+f"(c[2]), "+f"(c[3])
        : "r"(a[0]), "r"(a[1]), "r"(a[2]), "r"(a[3]), "r"(b[0]), "r"(b[1]));
}
__device__ __forceinline__ float silu_f(float x) { return x / (1.0f + __expf(-x)); }
__device__ __forceinline__ int bswz(int k, int cb) { return (cb & 8) | ((cb ^ k) & 7); }

__global__ __launch_bounds__(256, 2) void gemm_silu_kernel(const float* __restrict__ bias,
                                                           float* __restrict__ out) {
    extern __shared__ char smem[];
    uint32_t sb = smem_u32(smem);
    int tid = threadIdx.x;
    int wid = tid >> 5;
    int lane = tid & 31;

    int v0 = blockIdx.x * 128;           // vt fastest -> 4 CTAs share B tile in L2
    int l0 = blockIdx.y * 128;
    int b  = blockIdx.z;

    int wm = wid & 1;
    int wn = wid >> 1;

    const __half* Yh = (const __half*)g_Yhi;
    const __half* Wh = (const __half*)g_Whi;

    float acc[4][4][4];
#pragma unroll
    for (int i = 0; i < 4; i++)
#pragma unroll
        for (int j = 0; j < 4; j++)
#pragma unroll
            for (int q = 0; q < 4; q++) acc[i][j][q] = 0.f;

    int ar  = tid >> 1;
    int ab  = (tid & 1) * 2;
    int bk  = tid >> 4;
    int bcb = tid & 15;

    auto load_hc = [&](int hc, int s) {
        int k0 = hc * HC;
        uint32_t base = sb + s * ST_SZ;
#pragma unroll
        for (int i = 0; i < 2; i++) {
            int blk = ab + i;
            size_t ga = (size_t)(v0 + ar) * Hh + k0 + blk * 8;
            cpa16(base + ar * A_ST + blk * 16, Wh + ga);
        }
#pragma unroll
        for (int g = 0; g < 2; g++) {
            int k = bk + g * 16;
            size_t ge = ((size_t)(b * Hh) + k0 + k) * Ll + l0 + bcb * 8;
            cpa16(base + 10240 + k * 256 + bswz(k, bcb) * 16, Yh + ge);
        }
    };

    load_hc(0, 0);
    asm volatile("cp.async.commit_group;" ::: "memory");
    load_hc(1, 1);
    asm volatile("cp.async.commit_group;" ::: "memory");

    for (int hc = 0; hc < NHC; hc++) {
        if (hc < NHC - 1) {
            asm volatile("cp.async.wait_group 1;" ::: "memory");
        } else {
            asm volatile("cp.async.wait_group 0;" ::: "memory");
        }
        __syncthreads();
        if (hc + 2 < NHC) {
            load_hc(hc + 2, (hc + 2) % 3);
            asm volatile("cp.async.commit_group;" ::: "memory");
        }

        uint32_t abase = sb + (hc % 3) * ST_SZ;
        uint32_t bbase = abase + 10240;
#pragma unroll
        for (int ks = 0; ks < 2; ks++) {
            uint32_t bh[2][4];
#pragma unroll
            for (int g = 0; g < 2; g++) {
                int krow = ks * 16 + (lane & 15);
                int cb = wn * 4 + g * 2 + (lane >> 4);
                uint32_t baddr = bbase + krow * 256 + bswz(krow, cb) * 16;
                ldsm4t(bh[g], baddr);
            }
#pragma unroll
            for (int mt = 0; mt < 4; mt++) {
                int arow = wm * 64 + mt * 16 + (lane & 15);
                uint32_t aaddr = abase + arow * A_ST + ks * 32 + (lane >> 4) * 16;
                uint32_t ahf[4];
                ldsm4(ahf, aaddr);
#pragma unroll
                for (int nt = 0; nt < 4; nt++) {
                    const uint32_t* bhx = &bh[nt >> 1][(nt & 1) * 2];
                    mma16816h(acc[mt][nt], ahf, bhx);
                }
            }
        }
    }

    __syncthreads();
    int g = lane >> 2;
    int cq = (lane & 3) * 2;
#pragma unroll
    for (int mt = 0; mt < 4; mt++) {
        int vbase = v0 + wm * 64 + mt * 16 + g;
        float bv0 = bias[vbase];
        float bv1 = bias[vbase + 8];
        float* row0 = out + ((size_t)(b * Hh) + vbase) * Ll;
        float* row1 = row0 + 8 * Ll;
#pragma unroll
        for (int nt = 0; nt < 4; nt++) {
            int lc = l0 + wn * 32 + nt * 8 + cq;
            float2 o0, o1;
            o0.x = silu_f(acc[mt][nt][0] + bv0);
            o0.y = silu_f(acc[mt][nt][1] + bv0);
            o1.x = silu_f(acc[mt][nt][2] + bv1);
            o1.y = silu_f(acc[mt][nt][3] + bv1);
            *(float2*)(row0 + lc) = o0;
            *(float2*)(row1 + lc) = o1;
        }
    }
}

extern "C" void kernel_launch(void* const* d_in, const int* in_sizes, int n_in,
                              void* d_out, int out_size) {
    const float* u    = (const float*)d_in[0];   // (16, 512, 4096)
    const float* kern = (const float*)d_in[1];   // (1, 512, 4096)
    const float* D    = (const float*)d_in[2];   // (1, 512)
    const float* Wout = (const float*)d_in[3];   // (512, 512)
    const float* bout = (const float*)d_in[4];   // (512,)
    float* out = (float*)d_out;                  // (16, 512, 4096)

    cudaFuncSetAttribute(gemm_silu_kernel, cudaFuncAttributeMaxDynamicSharedMemorySize, GEMM_SMEM);
    cudaFuncSetAttribute(conv_kernel, cudaFuncAttributeMaxDynamicSharedMemorySize, CONV_SMEM);

    build_kf_kernel<<<Hh, 512>>>(kern);
    split_w_kernel<<<256, 256>>>(Wout);
    conv_kernel<<<dim3(Hh, Bb), 512, CONV_SMEM>>>(u, D);
    gemm_silu_kernel<<<dim3(4, 32, 16), 256, GEMM_SMEM>>>(bout, out);
}